// round 17
// baseline (speedup 1.0000x reference)
#include <cuda_runtime.h>
#include <cuda_bf16.h>

// Problem shape (fixed by the dataset)
#define B_DIM 16
#define S_DIM 2048
#define D_DIM 256
#define ROWS  (B_DIM * S_DIM)          // 32768
#define P_ASEM 0.6f
#define Q_ASEM 0.4f
#define MASK_FILL 1e-9f

// Scratch for projected scores (no cudaMalloc allowed)
__device__ float g_si[ROWS];  // si + bias folded in
__device__ float g_sj[ROWS];

// ---------------------------------------------------------------------------
// 256-bit global memory ops (Blackwell sm_100+; PTX ISA 8.8 .v8.f32)
// ---------------------------------------------------------------------------
__device__ __forceinline__ void ldg256_cs(const float* p, float4& a, float4& b) {
    asm volatile("ld.global.cs.v8.f32 {%0,%1,%2,%3,%4,%5,%6,%7}, [%8];"
                 : "=f"(a.x), "=f"(a.y), "=f"(a.z), "=f"(a.w),
                   "=f"(b.x), "=f"(b.y), "=f"(b.z), "=f"(b.w)
                 : "l"(p));
}
__device__ __forceinline__ void stg256_cs(float* p, const float4& a, const float4& b) {
    asm volatile("st.global.cs.v8.f32 [%0], {%1,%2,%3,%4,%5,%6,%7,%8};"
                 :: "l"(p),
                    "f"(a.x), "f"(a.y), "f"(a.z), "f"(a.w),
                    "f"(b.x), "f"(b.y), "f"(b.z), "f"(b.w)
                 : "memory");
}

// ---------------------------------------------------------------------------
// Kernel 1: dual dot products, 4 rows per warp, masked-row skip (proven R10).
// ---------------------------------------------------------------------------
#define PROJ_RPW 4   // rows per warp

__global__ __launch_bounds__(256) void proj_kernel(const float* __restrict__ x,
                                                   const int*   __restrict__ mask,
                                                   const float* __restrict__ W,
                                                   const float* __restrict__ bias) {
    const int warp = blockIdx.x * (blockDim.x >> 5) + (threadIdx.x >> 5);
    const int lane = threadIdx.x & 31;
    const int row0 = warp * PROJ_RPW;

    int mrow[PROJ_RPW];
#pragma unroll
    for (int r = 0; r < PROJ_RPW; ++r) mrow[r] = __ldg(&mask[row0 + r]);

    const float4* Wi4 = reinterpret_cast<const float4*>(W);            // W[0:256]
    const float4* Wj4 = reinterpret_cast<const float4*>(W + D_DIM);    // W[256:512]

    float4 xv[PROJ_RPW][2];
#pragma unroll
    for (int r = 0; r < PROJ_RPW; ++r) {
        if (mrow[r]) {
            const float4* x4 = reinterpret_cast<const float4*>(x) +
                               (long)(row0 + r) * (D_DIM / 4);
            xv[r][0] = x4[lane];
            xv[r][1] = x4[lane + 32];
        }
    }

    const float4 wi0 = __ldg(&Wi4[lane]);
    const float4 wi1 = __ldg(&Wi4[lane + 32]);
    const float4 wj0 = __ldg(&Wj4[lane]);
    const float4 wj1 = __ldg(&Wj4[lane + 32]);

    float si[PROJ_RPW], sj[PROJ_RPW];
#pragma unroll
    for (int r = 0; r < PROJ_RPW; ++r) {
        if (!mrow[r]) { si[r] = 0.f; sj[r] = 0.f; continue; }
        float a = 0.f, b2 = 0.f;
        a = fmaf(xv[r][0].x, wi0.x, a); a = fmaf(xv[r][0].y, wi0.y, a);
        a = fmaf(xv[r][0].z, wi0.z, a); a = fmaf(xv[r][0].w, wi0.w, a);
        a = fmaf(xv[r][1].x, wi1.x, a); a = fmaf(xv[r][1].y, wi1.y, a);
        a = fmaf(xv[r][1].z, wi1.z, a); a = fmaf(xv[r][1].w, wi1.w, a);
        b2 = fmaf(xv[r][0].x, wj0.x, b2); b2 = fmaf(xv[r][0].y, wj0.y, b2);
        b2 = fmaf(xv[r][0].z, wj0.z, b2); b2 = fmaf(xv[r][0].w, wj0.w, b2);
        b2 = fmaf(xv[r][1].x, wj1.x, b2); b2 = fmaf(xv[r][1].y, wj1.y, b2);
        b2 = fmaf(xv[r][1].z, wj1.z, b2); b2 = fmaf(xv[r][1].w, wj1.w, b2);
        si[r] = a; sj[r] = b2;
    }

#pragma unroll
    for (int off = 16; off > 0; off >>= 1) {
#pragma unroll
        for (int r = 0; r < PROJ_RPW; ++r) {
            if (mrow[r]) {
                si[r] += __shfl_down_sync(0xFFFFFFFFu, si[r], off);
                sj[r] += __shfl_down_sync(0xFFFFFFFFu, sj[r], off);
            }
        }
    }
    if (lane == 0) {
        const float bv = __ldg(bias);
#pragma unroll
        for (int r = 0; r < PROJ_RPW; ++r) {
            if (mrow[r]) {
                g_si[row0 + r] = si[r] + bv;
                g_sj[row0 + r] = sj[r];
            }
        }
    }
}

// ---------------------------------------------------------------------------
// Kernel 2: 512 threads, RPB=4 (8192 blocks, proven shape), 256-bit accesses.
// Thread layout: h = tid>>8 selects row parity; each thread handles rows
// {row0+h, row0+h+2} at float offset (tid&255)*8 (32B-aligned). Per-thread
// traffic unchanged (2x32B loads in flight), instruction count halved.
// Unified store path: masked rows produce MASK_FILL through the same code.
// ---------------------------------------------------------------------------
__device__ __forceinline__ float sig_blend(float si, float sjv, int m, float a) {
    float z = si + sjv;
    float s = __fdividef(1.f, 1.f + __expf(-z));
    return m ? fmaf(P_ASEM, s, Q_ASEM * a) : MASK_FILL;
}

__global__ __launch_bounds__(512) void fuse_kernel(const float* __restrict__ adj,
                                                   const int*   __restrict__ mask,
                                                   float*       __restrict__ out) {
    const unsigned tid  = threadIdx.x;                 // 0..511
    const unsigned h    = tid >> 8;                    // 0 or 1
    const unsigned t8   = (tid & 255u) << 3;           // float offset in row (32B mult)
    const unsigned row0 = blockIdx.x << 2;             // 4 rows, same batch
    const unsigned rA   = row0 + h;
    const unsigned rB   = row0 + h + 2;

    const int miA = mask[rA];
    const int miB = mask[rB];

    const size_t oA = ((size_t)rA << 11) + t8;
    const size_t oB = ((size_t)rB << 11) + t8;

    // 256-bit adj loads, predicated (both issued before any compute)
    float4 aA0, aA1, aB0, aB1;
    if (miA) ldg256_cs(adj + oA, aA0, aA1);
    else     { aA0 = make_float4(0,0,0,0); aA1 = aA0; }
    if (miB) ldg256_cs(adj + oB, aB0, aB1);
    else     { aB0 = make_float4(0,0,0,0); aB1 = aB0; }

    // column vectors (same for both rows of this thread)
    const unsigned b  = row0 >> 11;                    // batch
    const unsigned c4 = (b << 9) + ((tid & 255u) << 1); // float4 index into columns
    const float4* sj4 = reinterpret_cast<const float4*>(g_sj);
    const int4*   mj4 = reinterpret_cast<const int4*>(mask);
    const float4 sj0 = __ldg(&sj4[c4]);
    const float4 sj1 = __ldg(&sj4[c4 + 1]);
    const int4   mj0 = __ldg(&mj4[c4]);
    const int4   mj1 = __ldg(&mj4[c4 + 1]);

    const float siA = miA ? g_si[rA] : 0.f;
    const float siB = miB ? g_si[rB] : 0.f;

    float4 o0, o1;
    // row A
    o0.x = sig_blend(siA, sj0.x, miA & mj0.x, aA0.x);
    o0.y = sig_blend(siA, sj0.y, miA & mj0.y, aA0.y);
    o0.z = sig_blend(siA, sj0.z, miA & mj0.z, aA0.z);
    o0.w = sig_blend(siA, sj0.w, miA & mj0.w, aA0.w);
    o1.x = sig_blend(siA, sj1.x, miA & mj1.x, aA1.x);
    o1.y = sig_blend(siA, sj1.y, miA & mj1.y, aA1.y);
    o1.z = sig_blend(siA, sj1.z, miA & mj1.z, aA1.z);
    o1.w = sig_blend(siA, sj1.w, miA & mj1.w, aA1.w);
    stg256_cs(out + oA, o0, o1);

    // row B
    o0.x = sig_blend(siB, sj0.x, miB & mj0.x, aB0.x);
    o0.y = sig_blend(siB, sj0.y, miB & mj0.y, aB0.y);
    o0.z = sig_blend(siB, sj0.z, miB & mj0.z, aB0.z);
    o0.w = sig_blend(siB, sj0.w, miB & mj0.w, aB0.w);
    o1.x = sig_blend(siB, sj1.x, miB & mj1.x, aB1.x);
    o1.y = sig_blend(siB, sj1.y, miB & mj1.y, aB1.y);
    o1.z = sig_blend(siB, sj1.z, miB & mj1.z, aB1.z);
    o1.w = sig_blend(siB, sj1.w, miB & mj1.w, aB1.w);
    stg256_cs(out + oB, o0, o1);
}

// ---------------------------------------------------------------------------
// Launch
// Inputs (metadata order): 0:x [16,2048,256] f32, 1:adj [16,2048,2048] f32,
//                          2:mask [16,2048] i32, 3:W [1,512] f32, 4:b [1] f32
// Output: [16,2048,2048] f32
// ---------------------------------------------------------------------------
extern "C" void kernel_launch(void* const* d_in, const int* in_sizes, int n_in,
                              void* d_out, int out_size) {
    const float* x    = (const float*)d_in[0];
    const float* adj  = (const float*)d_in[1];
    const int*   mask = (const int*)d_in[2];
    const float* W    = (const float*)d_in[3];
    const float* bias = (const float*)d_in[4];
    float* out = (float*)d_out;

    // Kernel 1: 4 rows/warp, 8 warps/block -> 32 rows/block -> 1024 blocks
    proj_kernel<<<ROWS / (PROJ_RPW * 8), 256>>>(x, mask, W, bias);

    // Kernel 2: one block per 4 output rows -> 8192 blocks of 512 threads
    fuse_kernel<<<ROWS / 4, 512>>>(adj, mask, out);
}